// round 7
// baseline (speedup 1.0000x reference)
#include <cuda_runtime.h>

#define NN 50000          // nodes
#define NE 1600000        // edges
#define TOT (NE + NN)     // edges + self loops
#define KDIM 1028
#define DOUT 256
#define NEG 0.2f
#define NBS ((NN + 511) / 512)   // scan blocks = 98

// ---------------- scratch (static device globals; no allocation) ----------------
__device__ float g_xl[(size_t)NN * DOUT];
__device__ float g_xr[(size_t)NN * DOUT];
__device__ int   g_counts[NN];
__device__ int   g_starts[NN];
__device__ int   g_work[NN];
__device__ int   g_src_sorted[TOT];
__device__ int   g_bsum[NBS];
__device__ int   g_is64;          // edge_index dtype flag (detected at runtime)

// ---------------- edge dtype detection ----------------
// Reference uses jnp.int64, but JAX downcasts to int32 unless x64 is enabled.
// Detect the actual layout: int64 little-endian => every odd 32-bit word of the
// first 64 entries is 0 (values are < 50000). For int32 data those words are
// random edge ids — 64 consecutive zeros has probability ~(1/50000)^64 ~ 0.
__global__ void k_detect(const int* __restrict__ e32) {
    if (threadIdx.x == 0 && blockIdx.x == 0) {
        int is64 = 1;
        for (int i = 0; i < 64; i++) {
            if (e32[2 * i + 1] != 0) { is64 = 0; break; }
        }
        g_is64 = is64;
    }
}

__device__ __forceinline__ int edge_at(const void* ei, int idx) {
    if (g_is64) return (int)((const long long*)ei)[idx];
    return ((const int*)ei)[idx];
}

// ---------------- CSR build: histogram / scan / scatter ----------------
__global__ void k_zero_counts() {
    int i = blockIdx.x * blockDim.x + threadIdx.x;
    if (i < NN) g_counts[i] = 0;
}

__global__ void k_hist(const void* __restrict__ ei) {
    int k = blockIdx.x * blockDim.x + threadIdx.x;
    if (k >= TOT) return;
    int dst = (k < NE) ? edge_at(ei, NE + k) : (k - NE);
    if ((unsigned)dst < NN) atomicAdd(&g_counts[dst], 1);
}

__global__ void k_scan1() {
    __shared__ int sh[512];
    int t = threadIdx.x;
    int i = blockIdx.x * 512 + t;
    int v = (i < NN) ? g_counts[i] : 0;
    sh[t] = v;
    __syncthreads();
    #pragma unroll
    for (int o = 1; o < 512; o <<= 1) {
        int u = (t >= o) ? sh[t - o] : 0;
        __syncthreads();
        sh[t] += u;
        __syncthreads();
    }
    if (i < NN) g_starts[i] = sh[t] - v;   // exclusive within block
    if (t == 511) g_bsum[blockIdx.x] = sh[t];
}

__global__ void k_scan2() {
    if (threadIdx.x == 0 && blockIdx.x == 0) {
        int run = 0;
        for (int b = 0; b < NBS; b++) {
            int c = g_bsum[b];
            g_bsum[b] = run;
            run += c;
        }
    }
}

__global__ void k_scan3() {
    int i = blockIdx.x * blockDim.x + threadIdx.x;
    if (i >= NN) return;
    int s = g_starts[i] + g_bsum[i >> 9];
    g_starts[i] = s;
    g_work[i] = s;
}

__global__ void k_scatter(const void* __restrict__ ei) {
    int k = blockIdx.x * blockDim.x + threadIdx.x;
    if (k >= TOT) return;
    int src, dst;
    if (k < NE) { src = edge_at(ei, k); dst = edge_at(ei, NE + k); }
    else        { src = k - NE;         dst = k - NE; }
    if ((unsigned)dst >= NN || (unsigned)src >= NN) return;
    int pos = atomicAdd(&g_work[dst], 1);
    g_src_sorted[pos] = src;
}

// ---------------- fused dual GEMM: xl = x@Wl, xr = x@Wr ----------------
// BM=128, BN=128, BK=8, 256 threads, 8x8 per thread, f32x2 packed FMAs
// (fma.rn.f32x2 is sm_103a-only; 2x scalar FFMA throughput).
// grid.y: 0,1 -> Wl cols [0,128),[128,256);  2,3 -> Wr.
__global__ __launch_bounds__(256, 1) void k_gemm(
    const float* __restrict__ X,
    const float* __restrict__ Wl,
    const float* __restrict__ Wr)
{
    const int by = blockIdx.y;
    const float* __restrict__ W = (by < 2) ? Wl : Wr;
    float* __restrict__ O = (by < 2) ? g_xl : g_xr;
    const int col0 = (by & 1) * 128;
    const int m0 = blockIdx.x * 128;

    __shared__ __align__(16) float As[2][8][128];
    __shared__ __align__(16) float Bs[2][8][128];

    const int t = threadIdx.x;
    const int arow = t >> 1;          // 0..127
    const int akg  = (t & 1) * 4;     // 0 or 4
    const int bk   = t >> 5;          // 0..7
    const int bc   = (t & 31) * 4;    // 0..124
    const int tx = t & 15, ty = t >> 4;

    unsigned long long acc2[8][4];
    #pragma unroll
    for (int i = 0; i < 8; i++)
        #pragma unroll
        for (int p = 0; p < 4; p++) acc2[i][p] = 0ULL;

    const int KT = (KDIM + 7) / 8;    // 129 (last tile has 4 valid k)
    const bool rowOK = (m0 + arow) < NN;

    float4 aReg = make_float4(0.f, 0.f, 0.f, 0.f);
    float4 bReg = make_float4(0.f, 0.f, 0.f, 0.f);
    // prefetch tile 0
    if (rowOK) aReg = *(const float4*)(X + (size_t)(m0 + arow) * KDIM + akg);
    bReg = *(const float4*)(W + (size_t)bk * DOUT + col0 + bc);

    As[0][akg + 0][arow] = aReg.x;
    As[0][akg + 1][arow] = aReg.y;
    As[0][akg + 2][arow] = aReg.z;
    As[0][akg + 3][arow] = aReg.w;
    *(float4*)&Bs[0][bk][bc] = bReg;
    __syncthreads();

    for (int kt = 0; kt < KT; kt++) {
        const int buf = kt & 1;
        float4 aN = make_float4(0.f, 0.f, 0.f, 0.f);
        float4 bN = make_float4(0.f, 0.f, 0.f, 0.f);
        if (kt + 1 < KT) {
            int k0n = (kt + 1) * 8;
            if (rowOK && (k0n + akg) < KDIM)
                aN = *(const float4*)(X + (size_t)(m0 + arow) * KDIM + k0n + akg);
            if ((k0n + bk) < KDIM)
                bN = *(const float4*)(W + (size_t)(k0n + bk) * DOUT + col0 + bc);
        }

        #pragma unroll
        for (int kk = 0; kk < 8; kk++) {
            float4 a0 = *(const float4*)&As[buf][kk][ty * 8];
            float4 a1 = *(const float4*)&As[buf][kk][ty * 8 + 4];
            const ulonglong2* bp = (const ulonglong2*)&Bs[buf][kk][tx * 8];
            ulonglong2 q0 = bp[0], q1 = bp[1];
            unsigned long long b2[4] = {q0.x, q0.y, q1.x, q1.y};
            float av[8] = {a0.x, a0.y, a0.z, a0.w, a1.x, a1.y, a1.z, a1.w};
            #pragma unroll
            for (int i = 0; i < 8; i++) {
                unsigned long long a2;
                asm("mov.b64 %0, {%1, %1};" : "=l"(a2) : "f"(av[i]));
                #pragma unroll
                for (int p = 0; p < 4; p++) {
                    asm("fma.rn.f32x2 %0, %1, %2, %0;"
                        : "+l"(acc2[i][p]) : "l"(a2), "l"(b2[p]));
                }
            }
        }

        if (kt + 1 < KT) {
            __syncthreads();
            int nbuf = buf ^ 1;
            As[nbuf][akg + 0][arow] = aN.x;
            As[nbuf][akg + 1][arow] = aN.y;
            As[nbuf][akg + 2][arow] = aN.z;
            As[nbuf][akg + 3][arow] = aN.w;
            *(float4*)&Bs[nbuf][bk][bc] = bN;
            __syncthreads();
        }
    }

    // epilogue
    #pragma unroll
    for (int i = 0; i < 8; i++) {
        int m = m0 + ty * 8 + i;
        if (m < NN) {
            float* op = O + (size_t)m * DOUT + col0 + tx * 8;
            float4 o0, o1;
            o0.x = __uint_as_float((unsigned)acc2[i][0]);
            o0.y = __uint_as_float((unsigned)(acc2[i][0] >> 32));
            o0.z = __uint_as_float((unsigned)acc2[i][1]);
            o0.w = __uint_as_float((unsigned)(acc2[i][1] >> 32));
            o1.x = __uint_as_float((unsigned)acc2[i][2]);
            o1.y = __uint_as_float((unsigned)(acc2[i][2] >> 32));
            o1.z = __uint_as_float((unsigned)acc2[i][3]);
            o1.w = __uint_as_float((unsigned)(acc2[i][3] >> 32));
            *(float4*)(op)     = o0;
            *(float4*)(op + 4) = o1;
        }
    }
}

// ---------------- fused attention softmax + aggregation ----------------
// One warp per destination node. Lane owns 8 feature dims.
// Softmax max-subtraction omitted: alpha = p/sum(p) is shift-invariant and
// |e| is O(10) here, so fp32 exp is safe. Inner loop pipelined 2 deep.
__global__ __launch_bounds__(256) void k_aggregate(
    const float* __restrict__ att,
    const float* __restrict__ bias,
    float* __restrict__ out)
{
    const int gw = (blockIdx.x * blockDim.x + threadIdx.x) >> 5;  // node id
    const int lane = threadIdx.x & 31;
    if (gw >= NN) return;

    const int base = lane * 8;
    float4 xr0 = *(const float4*)(g_xr + (size_t)gw * DOUT + base);
    float4 xr1 = *(const float4*)(g_xr + (size_t)gw * DOUT + base + 4);
    float4 at0 = *(const float4*)(att + base);
    float4 at1 = *(const float4*)(att + base + 4);

    float a0 = 0.f, a1 = 0.f, a2 = 0.f, a3 = 0.f;
    float a4 = 0.f, a5 = 0.f, a6 = 0.f, a7 = 0.f;
    float denom = 0.f;

    const int s = g_starts[gw];
    const int cnt = g_counts[gw];

    for (int b = 0; b < cnt; b += 32) {
        int m = cnt - b; if (m > 32) m = 32;
        int sidx = 0;
        if (b + lane < cnt) sidx = g_src_sorted[s + b + lane];

        // prologue: gather edge 0 of this batch
        int src0 = __shfl_sync(0xffffffffu, sidx, 0);
        const float4* xp = (const float4*)(g_xl + (size_t)src0 * DOUT + base);
        float4 v0 = __ldg(xp);
        float4 v1 = __ldg(xp + 1);

        for (int j = 0; j < m; j++) {
            float4 c0 = v0, c1 = v1;
            if (j + 1 < m) {
                int srcn = __shfl_sync(0xffffffffu, sidx, j + 1);
                const float4* xn = (const float4*)(g_xl + (size_t)srcn * DOUT + base);
                v0 = __ldg(xn);          // in flight while computing edge j
                v1 = __ldg(xn + 1);
            }

            float e = 0.f, z, l;
            z = c0.x + xr0.x; l = fmaxf(z, NEG * z); e = fmaf(l, at0.x, e);
            z = c0.y + xr0.y; l = fmaxf(z, NEG * z); e = fmaf(l, at0.y, e);
            z = c0.z + xr0.z; l = fmaxf(z, NEG * z); e = fmaf(l, at0.z, e);
            z = c0.w + xr0.w; l = fmaxf(z, NEG * z); e = fmaf(l, at0.w, e);
            z = c1.x + xr1.x; l = fmaxf(z, NEG * z); e = fmaf(l, at1.x, e);
            z = c1.y + xr1.y; l = fmaxf(z, NEG * z); e = fmaf(l, at1.y, e);
            z = c1.z + xr1.z; l = fmaxf(z, NEG * z); e = fmaf(l, at1.z, e);
            z = c1.w + xr1.w; l = fmaxf(z, NEG * z); e = fmaf(l, at1.w, e);

            e += __shfl_xor_sync(0xffffffffu, e, 16);
            e += __shfl_xor_sync(0xffffffffu, e, 8);
            e += __shfl_xor_sync(0xffffffffu, e, 4);
            e += __shfl_xor_sync(0xffffffffu, e, 2);
            e += __shfl_xor_sync(0xffffffffu, e, 1);

            float p = __expf(e);
            denom += p;
            a0 = fmaf(p, c0.x, a0); a1 = fmaf(p, c0.y, a1);
            a2 = fmaf(p, c0.z, a2); a3 = fmaf(p, c0.w, a3);
            a4 = fmaf(p, c1.x, a4); a5 = fmaf(p, c1.y, a5);
            a6 = fmaf(p, c1.z, a6); a7 = fmaf(p, c1.w, a7);
        }
    }

    float r = 1.0f / denom;
    float4 b0 = *(const float4*)(bias + base);
    float4 b1 = *(const float4*)(bias + base + 4);
    float4 o0, o1;
    o0.x = fmaf(a0, r, b0.x); o0.y = fmaf(a1, r, b0.y);
    o0.z = fmaf(a2, r, b0.z); o0.w = fmaf(a3, r, b0.w);
    o1.x = fmaf(a4, r, b1.x); o1.y = fmaf(a5, r, b1.y);
    o1.z = fmaf(a6, r, b1.z); o1.w = fmaf(a7, r, b1.w);
    float* op = out + (size_t)gw * DOUT + base;
    *(float4*)(op)     = o0;
    *(float4*)(op + 4) = o1;
}

// ---------------- launch ----------------
extern "C" void kernel_launch(void* const* d_in, const int* in_sizes, int n_in,
                              void* d_out, int out_size) {
    const float* x    = (const float*)d_in[0];
    const void*  ei   = d_in[1];                    // int32 or int64 (detected)
    const float* Wl   = (const float*)d_in[2];
    const float* Wr   = (const float*)d_in[3];
    const float* att  = (const float*)d_in[4];
    const float* bias = (const float*)d_in[5];
    float*       out  = (float*)d_out;

    // dtype detection + CSR build (~60us)
    k_detect<<<1, 32>>>((const int*)ei);
    k_zero_counts<<<(NN + 255) / 256, 256>>>();
    k_hist<<<(TOT + 255) / 256, 256>>>(ei);
    k_scan1<<<NBS, 512>>>();
    k_scan2<<<1, 32>>>();
    k_scan3<<<(NN + 255) / 256, 256>>>();
    k_scatter<<<(TOT + 255) / 256, 256>>>(ei);

    // xl / xr  (dominant cost; f32x2-packed SGEMM)
    dim3 gg((NN + 127) / 128, 4);
    k_gemm<<<gg, 256>>>(x, Wl, Wr);

    // fused softmax + aggregation (one warp per node; exact grid)
    k_aggregate<<<(NN * 32) / 256, 256>>>(att, bias, out);
}

// round 9
// speedup vs baseline: 1.8463x; 1.8463x over previous
#include <cuda_runtime.h>
#include <cuda_bf16.h>
#include <cstdint>

#define NN 50000          // nodes
#define NNP 50048         // padded to 128-multiple
#define NE 1600000        // edges
#define TOT (NE + NN)     // edges + self loops
#define KDIM 1028
#define KP 1088           // K padded (34 * 32)
#define DOUT 256
#define NEG 0.2f
#define NBS ((NN + 511) / 512)

#define BK 32
#define KT34 (KP / BK)            // 34 k-tiles
#define STG 32768                 // bytes per pipeline stage (Ah|Al|Bh|Bl, 8KB each)
#define SMEM_TOT (3 * STG)        // 96 KB, 3-stage pipeline

// ---------------- scratch (static device globals; zero-initialized) ----------------
__device__ float g_xl[(size_t)NNP * DOUT];
__device__ float g_xr[(size_t)NNP * DOUT];
__device__ unsigned short g_ah[(size_t)NNP * KP];   // X hi (bf16 bits), zero-padded
__device__ unsigned short g_al[(size_t)NNP * KP];   // X lo
__device__ unsigned short g_bh[512 * KP];           // W^T hi ([n][k]; n<256: Wl, else Wr)
__device__ unsigned short g_bl[512 * KP];           // W^T lo
__device__ int   g_counts[NN];
__device__ int   g_starts[NN];
__device__ int   g_work[NN];
__device__ int   g_src_sorted[TOT];
__device__ int   g_bsum[NBS];
__device__ int   g_is64;

// ---------------- small helpers ----------------
__device__ __forceinline__ unsigned short bfbits(float f) {
    __nv_bfloat16 h = __float2bfloat16(f);
    return *reinterpret_cast<unsigned short*>(&h);
}
__device__ __forceinline__ float bffloat(unsigned short u) {
    __nv_bfloat16 h = *reinterpret_cast<__nv_bfloat16*>(&u);
    return __bfloat162float(h);
}
__device__ __forceinline__ uint32_t smem_u32(const void* p) {
    uint32_t a;
    asm("{ .reg .u64 t; cvta.to.shared.u64 t, %1; cvt.u32.u64 %0, t; }" : "=r"(a) : "l"(p));
    return a;
}
__device__ __forceinline__ void cpa16(uint32_t s, const void* g) {
    asm volatile("cp.async.cg.shared.global [%0], [%1], 16;" :: "r"(s), "l"(g));
}
__device__ __forceinline__ void ldsm4(uint32_t addr, uint32_t* r) {
    asm volatile("ldmatrix.sync.aligned.m8n8.x4.shared.b16 {%0,%1,%2,%3}, [%4];"
                 : "=r"(r[0]), "=r"(r[1]), "=r"(r[2]), "=r"(r[3]) : "r"(addr));
}
__device__ __forceinline__ void mma16816(float* d, const uint32_t* a, uint32_t b0, uint32_t b1) {
    asm volatile(
        "mma.sync.aligned.m16n8k16.row.col.f32.bf16.bf16.f32 "
        "{%0,%1,%2,%3}, {%4,%5,%6,%7}, {%8,%9}, {%0,%1,%2,%3};"
        : "+f"(d[0]), "+f"(d[1]), "+f"(d[2]), "+f"(d[3])
        : "r"(a[0]), "r"(a[1]), "r"(a[2]), "r"(a[3]), "r"(b0), "r"(b1));
}
// 16B-chunk XOR swizzle: row stride 64B (4 chunks); conflict-free for ldmatrix 8-row reads
__device__ __forceinline__ uint32_t swaddr(uint32_t matbase, int row, int kchunk) {
    return matbase + row * 64 + ((kchunk ^ ((row >> 1) & 3)) * 16);
}

// ---------------- conversions: fp32 -> split bf16 (hi/lo), padded ----------------
__global__ void k_convA(const float* __restrict__ X) {
    size_t idx = (size_t)blockIdx.x * blockDim.x + threadIdx.x;
    const size_t total = (size_t)NN * (KP / 4);
    if (idx >= total) return;
    int row = (int)(idx / (KP / 4));
    int c4  = (int)(idx % (KP / 4)) * 4;
    float4 v = make_float4(0.f, 0.f, 0.f, 0.f);
    if (c4 < KDIM) v = *(const float4*)(X + (size_t)row * KDIM + c4);
    unsigned short h0 = bfbits(v.x), h1 = bfbits(v.y), h2 = bfbits(v.z), h3 = bfbits(v.w);
    unsigned short l0 = bfbits(v.x - bffloat(h0));
    unsigned short l1 = bfbits(v.y - bffloat(h1));
    unsigned short l2 = bfbits(v.z - bffloat(h2));
    unsigned short l3 = bfbits(v.w - bffloat(h3));
    uint2 hv, lv;
    hv.x = (uint32_t)h0 | ((uint32_t)h1 << 16);
    hv.y = (uint32_t)h2 | ((uint32_t)h3 << 16);
    lv.x = (uint32_t)l0 | ((uint32_t)l1 << 16);
    lv.y = (uint32_t)l2 | ((uint32_t)l3 << 16);
    *(uint2*)(g_ah + (size_t)row * KP + c4) = hv;
    *(uint2*)(g_al + (size_t)row * KP + c4) = lv;
}

__global__ void k_convB(const float* __restrict__ Wl, const float* __restrict__ Wr) {
    int idx = blockIdx.x * blockDim.x + threadIdx.x;
    if (idx >= 512 * KP) return;
    int n = idx / KP, k = idx % KP;
    float v = 0.f;
    if (k < KDIM) v = (n < 256) ? Wl[(size_t)k * 256 + n] : Wr[(size_t)k * 256 + (n - 256)];
    unsigned short h = bfbits(v);
    unsigned short l = bfbits(v - bffloat(h));
    g_bh[idx] = h;
    g_bl[idx] = l;
}

// ---------------- edge dtype detection (JAX may downcast int64->int32) ----------------
__global__ void k_detect(const int* __restrict__ e32) {
    if (threadIdx.x == 0 && blockIdx.x == 0) {
        int is64 = 1;
        for (int i = 0; i < 64; i++)
            if (e32[2 * i + 1] != 0) { is64 = 0; break; }
        g_is64 = is64;
    }
}
__device__ __forceinline__ int edge_at(const void* ei, int idx) {
    if (g_is64) return (int)((const long long*)ei)[idx];
    return ((const int*)ei)[idx];
}

// ---------------- CSR build ----------------
__global__ void k_zero_counts() {
    int i = blockIdx.x * blockDim.x + threadIdx.x;
    if (i < NN) g_counts[i] = 0;
}
__global__ void k_hist(const void* __restrict__ ei) {
    int k = blockIdx.x * blockDim.x + threadIdx.x;
    if (k >= TOT) return;
    int dst = (k < NE) ? edge_at(ei, NE + k) : (k - NE);
    if ((unsigned)dst < NN) atomicAdd(&g_counts[dst], 1);
}
__global__ void k_scan1() {
    __shared__ int sh[512];
    int t = threadIdx.x;
    int i = blockIdx.x * 512 + t;
    int v = (i < NN) ? g_counts[i] : 0;
    sh[t] = v;
    __syncthreads();
    #pragma unroll
    for (int o = 1; o < 512; o <<= 1) {
        int u = (t >= o) ? sh[t - o] : 0;
        __syncthreads();
        sh[t] += u;
        __syncthreads();
    }
    if (i < NN) g_starts[i] = sh[t] - v;
    if (t == 511) g_bsum[blockIdx.x] = sh[t];
}
__global__ void k_scan2() {
    if (threadIdx.x == 0 && blockIdx.x == 0) {
        int run = 0;
        for (int b = 0; b < NBS; b++) { int c = g_bsum[b]; g_bsum[b] = run; run += c; }
    }
}
__global__ void k_scan3() {
    int i = blockIdx.x * blockDim.x + threadIdx.x;
    if (i >= NN) return;
    int s = g_starts[i] + g_bsum[i >> 9];
    g_starts[i] = s;
    g_work[i] = s;
}
__global__ void k_scatter(const void* __restrict__ ei) {
    int k = blockIdx.x * blockDim.x + threadIdx.x;
    if (k >= TOT) return;
    int src, dst;
    if (k < NE) { src = edge_at(ei, k); dst = edge_at(ei, NE + k); }
    else        { src = k - NE;         dst = k - NE; }
    if ((unsigned)dst >= NN || (unsigned)src >= NN) return;
    int pos = atomicAdd(&g_work[dst], 1);
    g_src_sorted[pos] = src;
}

// ---------------- split-bf16 HMMA GEMM (mma.sync.m16n8k16) ----------------
// D = Ah@Bh^T + Ah@Bl^T + Al@Bh^T, fp32 accum shared across the 3 passes.
// CTA: BM=128 x BN=128, BK=32, 8 warps, warp tile 64x32.
// grid = (NNP/128, 4): by 0,1 -> g_xl cols [0,128),[128,256); by 2,3 -> g_xr.
__device__ __forceinline__ void load_stage(uint32_t sb, int buf, int kt, int m0, int n0, int t) {
    uint32_t base = sb + buf * STG;
    int k0 = kt * BK;
    #pragma unroll
    for (int p = 0; p < 8; p++) {
        int id = p * 256 + t;
        int mat = id >> 9;            // 0 Ah, 1 Al, 2 Bh, 3 Bl (constant per p)
        int cid = id & 511;
        int row = cid >> 2;
        int c = cid & 3;
        uint32_t dst = base + mat * 8192 + (uint32_t)row * 64 + ((c ^ ((row >> 1) & 3)) * 16);
        const unsigned short* src;
        if (mat == 0)      src = g_ah + (size_t)(m0 + row) * KP + k0 + c * 8;
        else if (mat == 1) src = g_al + (size_t)(m0 + row) * KP + k0 + c * 8;
        else if (mat == 2) src = g_bh + (size_t)(n0 + row) * KP + k0 + c * 8;
        else               src = g_bl + (size_t)(n0 + row) * KP + k0 + c * 8;
        cpa16(dst, src);
    }
}

__global__ __launch_bounds__(256, 1) void k_mma() {
    extern __shared__ __align__(128) char smem[];
    uint32_t sb = smem_u32(smem);
    const int t = threadIdx.x;
    const int warp = t >> 5, lane = t & 31;
    const int m0 = blockIdx.x * 128;
    const int by = blockIdx.y;
    const int n0 = by * 128;                      // row into 512-row g_bh/g_bl
    float* __restrict__ O = (by < 2) ? g_xl : g_xr;
    const int col0 = (by & 1) * 128;

    const int wm = (warp & 1) * 64;
    const int wn = (warp >> 1) * 32;

    float acc[4][4][4];
    #pragma unroll
    for (int mi = 0; mi < 4; mi++)
        #pragma unroll
        for (int ni = 0; ni < 4; ni++)
            #pragma unroll
            for (int q = 0; q < 4; q++) acc[mi][ni][q] = 0.f;

    // preload stages 0,1
    load_stage(sb, 0, 0, m0, n0, t);
    asm volatile("cp.async.commit_group;" ::: "memory");
    load_stage(sb, 1, 1, m0, n0, t);
    asm volatile("cp.async.commit_group;" ::: "memory");

    for (int kt = 0; kt < KT34; kt++) {
        if (kt < KT34 - 1) asm volatile("cp.async.wait_group 1;" ::: "memory");
        else               asm volatile("cp.async.wait_group 0;" ::: "memory");
        __syncthreads();   // stage kt visible; also: all warps done with stage kt-1's buffer

        if (kt + 2 < KT34) {
            load_stage(sb, (kt + 2) % 3, kt + 2, m0, n0, t);  // overwrites stage kt-1's buffer
            asm volatile("cp.async.commit_group;" ::: "memory");
        }

        uint32_t base = sb + (kt % 3) * STG;
        #pragma unroll
        for (int kk = 0; kk < 2; kk++) {
            uint32_t ah[4][4], al[4][4], bh[2][4], bl[2][4];
            const int kc = kk * 2 + (lane >> 4);
            #pragma unroll
            for (int fi = 0; fi < 4; fi++) {
                int row = wm + fi * 16 + (lane & 15);
                ldsm4(swaddr(base, row, kc), ah[fi]);
                ldsm4(swaddr(base + 8192, row, kc), al[fi]);
            }
            #pragma unroll
            for (int nf = 0; nf < 2; nf++) {
                int row = wn + nf * 16 + (lane & 15);
                ldsm4(swaddr(base + 16384, row, kc), bh[nf]);
                ldsm4(swaddr(base + 24576, row, kc), bl[nf]);
            }
            #pragma unroll
            for (int mi = 0; mi < 4; mi++)
                #pragma unroll
                for (int ni = 0; ni < 4; ni++) {
                    const int nf = ni >> 1, sel = ni & 1;
                    mma16816(acc[mi][ni], ah[mi], bh[nf][sel], bh[nf][sel + 2]);
                    mma16816(acc[mi][ni], ah[mi], bl[nf][sel], bl[nf][sel + 2]);
                    mma16816(acc[mi][ni], al[mi], bh[nf][sel], bh[nf][sel + 2]);
                }
        }
    }

    // epilogue: C frag -> fp32 stores (row m = l/4 (+8), col n = (l%4)*2)
    #pragma unroll
    for (int mi = 0; mi < 4; mi++) {
        int mrow0 = m0 + wm + mi * 16 + (lane >> 2);
        #pragma unroll
        for (int half = 0; half < 2; half++) {
            int m = mrow0 + half * 8;
            if (m < NN) {
                float* op = O + (size_t)m * DOUT + col0 + wn + (lane & 3) * 2;
                #pragma unroll
                for (int ni = 0; ni < 4; ni++) {
                    float2 v = make_float2(acc[mi][ni][half * 2], acc[mi][ni][half * 2 + 1]);
                    *(float2*)(op + ni * 8) = v;
                }
            }
        }
    }
}

// ---------------- fused attention softmax + aggregation ----------------
__global__ __launch_bounds__(256) void k_aggregate(
    const float* __restrict__ att,
    const float* __restrict__ bias,
    float* __restrict__ out)
{
    const int gw = (blockIdx.x * blockDim.x + threadIdx.x) >> 5;
    const int lane = threadIdx.x & 31;
    if (gw >= NN) return;

    const int base = lane * 8;
    float4 xr0 = *(const float4*)(g_xr + (size_t)gw * DOUT + base);
    float4 xr1 = *(const float4*)(g_xr + (size_t)gw * DOUT + base + 4);
    float4 at0 = *(const float4*)(att + base);
    float4 at1 = *(const float4*)(att + base + 4);

    float a0 = 0.f, a1 = 0.f, a2 = 0.f, a3 = 0.f;
    float a4 = 0.f, a5 = 0.f, a6 = 0.f, a7 = 0.f;
    float denom = 0.f;

    const int s = g_starts[gw];
    const int cnt = g_counts[gw];

    for (int b = 0; b < cnt; b += 32) {
        int m = cnt - b; if (m > 32) m = 32;
        int sidx = 0;
        if (b + lane < cnt) sidx = g_src_sorted[s + b + lane];

        int src0 = __shfl_sync(0xffffffffu, sidx, 0);
        const float4* xp = (const float4*)(g_xl + (size_t)src0 * DOUT + base);
        float4 v0 = __ldg(xp);
        float4 v1 = __ldg(xp + 1);

        for (int j = 0; j < m; j++) {
            float4 c0 = v0, c1 = v1;
            if (j + 1 < m) {
                int srcn = __shfl_sync(0xffffffffu, sidx, j + 1);
                const float4* xn = (const float4*)(g_xl + (size_t)srcn * DOUT + base);
                v0 = __ldg(xn);
                v1 = __ldg(xn + 1);
            }

            float e = 0.f, z, l;
            z = c0.x + xr0.x; l = fmaxf(z, NEG * z); e = fmaf(l, at0.x, e);
            z = c0.y + xr0.y; l = fmaxf(z, NEG * z); e = fmaf(l, at0.y, e);
            z = c0.z + xr0.z; l = fmaxf(z, NEG * z); e = fmaf(l, at0.z, e);
            z = c0.w + xr0.w; l = fmaxf(z, NEG * z); e = fmaf(l, at0.w, e);
            z = c1.x + xr1.x; l = fmaxf(z, NEG * z); e = fmaf(l, at1.x, e);
            z = c1.y + xr1.y; l = fmaxf(z, NEG * z); e = fmaf(l, at1.y, e);
            z = c1.z + xr1.z; l = fmaxf(z, NEG * z); e = fmaf(l, at1.z, e);
            z = c1.w + xr1.w; l = fmaxf(z, NEG * z); e = fmaf(l, at1.w, e);

            e += __shfl_xor_sync(0xffffffffu, e, 16);
            e += __shfl_xor_sync(0xffffffffu, e, 8);
            e += __shfl_xor_sync(0xffffffffu, e, 4);
            e += __shfl_xor_sync(0xffffffffu, e, 2);
            e += __shfl_xor_sync(0xffffffffu, e, 1);

            float p = __expf(e);
            denom += p;
            a0 = fmaf(p, c0.x, a0); a1 = fmaf(p, c0.y, a1);
            a2 = fmaf(p, c0.z, a2); a3 = fmaf(p, c0.w, a3);
            a4 = fmaf(p, c1.x, a4); a5 = fmaf(p, c1.y, a5);
            a6 = fmaf(p, c1.z, a6); a7 = fmaf(p, c1.w, a7);
        }
    }

    float r = 1.0f / denom;
    float4 b0 = *(const float4*)(bias + base);
    float4 b1 = *(const float4*)(bias + base + 4);
    float4 o0, o1;
    o0.x = fmaf(a0, r, b0.x); o0.y = fmaf(a1, r, b0.y);
    o0.z = fmaf(a2, r, b0.z); o0.w = fmaf(a3, r, b0.w);
    o1.x = fmaf(a4, r, b1.x); o1.y = fmaf(a5, r, b1.y);
    o1.z = fmaf(a6, r, b1.z); o1.w = fmaf(a7, r, b1.w);
    float* op = out + (size_t)gw * DOUT + base;
    *(float4*)(op)     = o0;
    *(float4*)(op + 4) = o1;
}

// ---------------- launch ----------------
extern "C" void kernel_launch(void* const* d_in, const int* in_sizes, int n_in,
                              void* d_out, int out_size) {
    const float* x    = (const float*)d_in[0];
    const void*  ei   = d_in[1];
    const float* Wl   = (const float*)d_in[2];
    const float* Wr   = (const float*)d_in[3];
    const float* att  = (const float*)d_in[4];
    const float* bias = (const float*)d_in[5];
    float*       out  = (float*)d_out;

    cudaFuncSetAttribute(k_mma, cudaFuncAttributeMaxDynamicSharedMemorySize, SMEM_TOT);

    // 1-5: conversions + CSR front half (k_mma is launch #6 -> profiled by -s 5 -c 1)
    {
        size_t tot = (size_t)NN * (KP / 4);
        k_convA<<<(unsigned)((tot + 255) / 256), 256>>>(x);
    }
    k_convB<<<(512 * KP + 255) / 256, 256>>>(Wl, Wr);
    k_detect<<<1, 32>>>((const int*)ei);
    k_zero_counts<<<(NN + 255) / 256, 256>>>();
    k_hist<<<(TOT + 255) / 256, 256>>>(ei);

    // 6: split-bf16 HMMA GEMM (xl / xr)
    k_mma<<<dim3(NNP / 128, 4), 256, SMEM_TOT>>>();

    // CSR back half
    k_scan1<<<NBS, 512>>>();
    k_scan2<<<1, 32>>>();
    k_scan3<<<(NN + 255) / 256, 256>>>();
    k_scatter<<<(TOT + 255) / 256, 256>>>(ei);

    // fused softmax + aggregation
    k_aggregate<<<(NN * 32) / 256, 256>>>(att, bias, out);
}

// round 10
// speedup vs baseline: 1.8862x; 1.0216x over previous
#include <cuda_runtime.h>
#include <cuda_bf16.h>
#include <cstdint>

#define NN 50000          // nodes
#define NNP 50048         // padded to 128-multiple
#define NE 1600000        // edges
#define TOT (NE + NN)     // edges + self loops
#define KDIM 1028
#define KP 1056           // K padded (33 * 32)
#define DOUT 256
#define NEG 0.2f
#define NBS ((NN + 511) / 512)

#define BK 32
#define KT (KP / BK)              // 33 k-tiles
#define STG 32768                 // bytes per pipeline stage (Ah|Al|Bh|Bl, 8KB each)
#define SMEM_TOT (3 * STG)        // 96 KB, 3-stage pipeline

// ---------------- scratch (static device globals; zero-initialized) ----------------
__device__ float g_xl[(size_t)NNP * DOUT];
__device__ float g_xr[(size_t)NNP * DOUT];
__device__ unsigned short g_ah[(size_t)NNP * KP];   // X hi (bf16 bits), zero-padded
__device__ unsigned short g_al[(size_t)NNP * KP];   // X lo
__device__ unsigned short g_bh[512 * KP];           // W^T hi ([n][k]; n<256: Wl, else Wr)
__device__ unsigned short g_bl[512 * KP];           // W^T lo
__device__ int   g_counts[NN];
__device__ int   g_starts[NN];
__device__ int   g_work[NN];
__device__ int   g_src_sorted[TOT];
__device__ int   g_bsum[NBS];
__device__ int   g_is64;

// ---------------- small helpers ----------------
__device__ __forceinline__ unsigned short bfbits(float f) {
    __nv_bfloat16 h = __float2bfloat16(f);
    return *reinterpret_cast<unsigned short*>(&h);
}
__device__ __forceinline__ float bffloat(unsigned short u) {
    __nv_bfloat16 h = *reinterpret_cast<__nv_bfloat16*>(&u);
    return __bfloat162float(h);
}
__device__ __forceinline__ uint32_t smem_u32(const void* p) {
    uint32_t a;
    asm("{ .reg .u64 t; cvta.to.shared.u64 t, %1; cvt.u32.u64 %0, t; }" : "=r"(a) : "l"(p));
    return a;
}
__device__ __forceinline__ void cpa16(uint32_t s, const void* g) {
    asm volatile("cp.async.cg.shared.global [%0], [%1], 16;" :: "r"(s), "l"(g));
}
__device__ __forceinline__ void ldsm4(uint32_t addr, uint32_t* r) {
    asm volatile("ldmatrix.sync.aligned.m8n8.x4.shared.b16 {%0,%1,%2,%3}, [%4];"
                 : "=r"(r[0]), "=r"(r[1]), "=r"(r[2]), "=r"(r[3]) : "r"(addr));
}
__device__ __forceinline__ void mma16816(float* d, const uint32_t* a, uint32_t b0, uint32_t b1) {
    asm volatile(
        "mma.sync.aligned.m16n8k16.row.col.f32.bf16.bf16.f32 "
        "{%0,%1,%2,%3}, {%4,%5,%6,%7}, {%8,%9}, {%0,%1,%2,%3};"
        : "+f"(d[0]), "+f"(d[1]), "+f"(d[2]), "+f"(d[3])
        : "r"(a[0]), "r"(a[1]), "r"(a[2]), "r"(a[3]), "r"(b0), "r"(b1));
}
// 16B-chunk XOR swizzle: row stride 64B (4 chunks); conflict-free for ldmatrix 8-row reads
__device__ __forceinline__ uint32_t swaddr(uint32_t matbase, int row, int kchunk) {
    return matbase + row * 64 + ((kchunk ^ ((row >> 1) & 3)) * 16);
}

// ---------------- conversions: fp32 -> split bf16 (hi/lo), padded ----------------
__global__ void k_convA(const float* __restrict__ X) {
    size_t idx = (size_t)blockIdx.x * blockDim.x + threadIdx.x;
    const size_t total = (size_t)NN * (KP / 4);
    if (idx >= total) return;
    int row = (int)(idx / (KP / 4));
    int c4  = (int)(idx % (KP / 4)) * 4;
    float4 v = make_float4(0.f, 0.f, 0.f, 0.f);
    if (c4 < KDIM) v = *(const float4*)(X + (size_t)row * KDIM + c4);
    unsigned short h0 = bfbits(v.x), h1 = bfbits(v.y), h2 = bfbits(v.z), h3 = bfbits(v.w);
    unsigned short l0 = bfbits(v.x - bffloat(h0));
    unsigned short l1 = bfbits(v.y - bffloat(h1));
    unsigned short l2 = bfbits(v.z - bffloat(h2));
    unsigned short l3 = bfbits(v.w - bffloat(h3));
    uint2 hv, lv;
    hv.x = (uint32_t)h0 | ((uint32_t)h1 << 16);
    hv.y = (uint32_t)h2 | ((uint32_t)h3 << 16);
    lv.x = (uint32_t)l0 | ((uint32_t)l1 << 16);
    lv.y = (uint32_t)l2 | ((uint32_t)l3 << 16);
    *(uint2*)(g_ah + (size_t)row * KP + c4) = hv;
    *(uint2*)(g_al + (size_t)row * KP + c4) = lv;
}

__global__ void k_convB(const float* __restrict__ Wl, const float* __restrict__ Wr) {
    int idx = blockIdx.x * blockDim.x + threadIdx.x;
    if (idx >= 512 * KP) return;
    int n = idx / KP, k = idx % KP;
    float v = 0.f;
    if (k < KDIM) v = (n < 256) ? Wl[(size_t)k * 256 + n] : Wr[(size_t)k * 256 + (n - 256)];
    unsigned short h = bfbits(v);
    unsigned short l = bfbits(v - bffloat(h));
    g_bh[idx] = h;
    g_bl[idx] = l;
}

// ---------------- edge dtype detection (JAX may downcast int64->int32) ----------------
__global__ void k_detect(const int* __restrict__ e32) {
    if (threadIdx.x == 0 && blockIdx.x == 0) {
        int is64 = 1;
        for (int i = 0; i < 64; i++)
            if (e32[2 * i + 1] != 0) { is64 = 0; break; }
        g_is64 = is64;
    }
}
__device__ __forceinline__ int edge_at(const void* ei, int idx) {
    if (g_is64) return (int)((const long long*)ei)[idx];
    return ((const int*)ei)[idx];
}

// ---------------- CSR build ----------------
__global__ void k_zero_counts() {
    int i = blockIdx.x * blockDim.x + threadIdx.x;
    if (i < NN) g_counts[i] = 0;
}
__global__ void k_hist(const void* __restrict__ ei) {
    int k = blockIdx.x * blockDim.x + threadIdx.x;
    if (k >= TOT) return;
    int dst = (k < NE) ? edge_at(ei, NE + k) : (k - NE);
    if ((unsigned)dst < NN) atomicAdd(&g_counts[dst], 1);
}
__global__ void k_scan1() {
    __shared__ int sh[512];
    int t = threadIdx.x;
    int i = blockIdx.x * 512 + t;
    int v = (i < NN) ? g_counts[i] : 0;
    sh[t] = v;
    __syncthreads();
    #pragma unroll
    for (int o = 1; o < 512; o <<= 1) {
        int u = (t >= o) ? sh[t - o] : 0;
        __syncthreads();
        sh[t] += u;
        __syncthreads();
    }
    if (i < NN) g_starts[i] = sh[t] - v;
    if (t == 511) g_bsum[blockIdx.x] = sh[t];
}
__global__ void k_scan2() {
    if (threadIdx.x == 0 && blockIdx.x == 0) {
        int run = 0;
        for (int b = 0; b < NBS; b++) { int c = g_bsum[b]; g_bsum[b] = run; run += c; }
    }
}
__global__ void k_scan3() {
    int i = blockIdx.x * blockDim.x + threadIdx.x;
    if (i >= NN) return;
    int s = g_starts[i] + g_bsum[i >> 9];
    g_starts[i] = s;
    g_work[i] = s;
}
__global__ void k_scatter(const void* __restrict__ ei) {
    int k = blockIdx.x * blockDim.x + threadIdx.x;
    if (k >= TOT) return;
    int src, dst;
    if (k < NE) { src = edge_at(ei, k); dst = edge_at(ei, NE + k); }
    else        { src = k - NE;         dst = k - NE; }
    if ((unsigned)dst >= NN || (unsigned)src >= NN) return;
    int pos = atomicAdd(&g_work[dst], 1);
    g_src_sorted[pos] = src;
}

// ---------------- split-bf16 HMMA GEMM (mma.sync.m16n8k16) ----------------
// D = Ah@Bh^T + Ah@Bl^T + Al@Bh^T, fp32 accum shared across the 3 passes.
// CTA: BM=128 x BN=128, BK=32, 8 warps, warp tile 64x32.
// grid = (4, NNP/128): bx 0,1 -> g_xl cols [0,128),[128,256); bx 2,3 -> g_xr.
// bx is the FAST grid dim so the 4 column-variants of one row-block are
// schedule-adjacent -> the A hi/lo tile is read from DRAM once and L2-hit 3x.
__device__ __forceinline__ void load_stage(uint32_t sb, int buf, int kt, int m0, int n0, int t) {
    uint32_t base = sb + buf * STG;
    int k0 = kt * BK;
    #pragma unroll
    for (int p = 0; p < 8; p++) {
        int id = p * 256 + t;
        int mat = id >> 9;            // 0 Ah, 1 Al, 2 Bh, 3 Bl (constant per p)
        int cid = id & 511;
        int row = cid >> 2;
        int c = cid & 3;
        uint32_t dst = base + mat * 8192 + (uint32_t)row * 64 + ((c ^ ((row >> 1) & 3)) * 16);
        const unsigned short* src;
        if (mat == 0)      src = g_ah + (size_t)(m0 + row) * KP + k0 + c * 8;
        else if (mat == 1) src = g_al + (size_t)(m0 + row) * KP + k0 + c * 8;
        else if (mat == 2) src = g_bh + (size_t)(n0 + row) * KP + k0 + c * 8;
        else               src = g_bl + (size_t)(n0 + row) * KP + k0 + c * 8;
        cpa16(dst, src);
    }
}

__global__ __launch_bounds__(256, 1) void k_mma() {
    extern __shared__ __align__(128) char smem[];
    uint32_t sb = smem_u32(smem);
    const int t = threadIdx.x;
    const int warp = t >> 5, lane = t & 31;
    const int by = blockIdx.x;                    // column-variant (fast dim)
    const int m0 = blockIdx.y * 128;              // row block
    const int n0 = by * 128;                      // row into 512-row g_bh/g_bl
    float* __restrict__ O = (by < 2) ? g_xl : g_xr;
    const int col0 = (by & 1) * 128;

    const int wm = (warp & 1) * 64;
    const int wn = (warp >> 1) * 32;

    float acc[4][4][4];
    #pragma unroll
    for (int mi = 0; mi < 4; mi++)
        #pragma unroll
        for (int ni = 0; ni < 4; ni++)
            #pragma unroll
            for (int q = 0; q < 4; q++) acc[mi][ni][q] = 0.f;

    // preload stages 0,1
    load_stage(sb, 0, 0, m0, n0, t);
    asm volatile("cp.async.commit_group;" ::: "memory");
    load_stage(sb, 1, 1, m0, n0, t);
    asm volatile("cp.async.commit_group;" ::: "memory");

    for (int kt = 0; kt < KT; kt++) {
        if (kt < KT - 1) asm volatile("cp.async.wait_group 1;" ::: "memory");
        else             asm volatile("cp.async.wait_group 0;" ::: "memory");
        __syncthreads();   // stage kt visible; all warps done with stage kt-1's buffer

        if (kt + 2 < KT) {
            load_stage(sb, (kt + 2) % 3, kt + 2, m0, n0, t);  // overwrites stage kt-1's buffer
            asm volatile("cp.async.commit_group;" ::: "memory");
        }

        uint32_t base = sb + (kt % 3) * STG;
        #pragma unroll
        for (int kk = 0; kk < 2; kk++) {
            uint32_t ah[4][4], al[4][4], bh[2][4], bl[2][4];
            const int kc = kk * 2 + (lane >> 4);
            #pragma unroll
            for (int fi = 0; fi < 4; fi++) {
                int row = wm + fi * 16 + (lane & 15);
                ldsm4(swaddr(base, row, kc), ah[fi]);
                ldsm4(swaddr(base + 8192, row, kc), al[fi]);
            }
            #pragma unroll
            for (int nf = 0; nf < 2; nf++) {
                int row = wn + nf * 16 + (lane & 15);
                ldsm4(swaddr(base + 16384, row, kc), bh[nf]);
                ldsm4(swaddr(base + 24576, row, kc), bl[nf]);
            }
            #pragma unroll
            for (int mi = 0; mi < 4; mi++)
                #pragma unroll
                for (int ni = 0; ni < 4; ni++) {
                    const int nf = ni >> 1, sel = ni & 1;
                    mma16816(acc[mi][ni], ah[mi], bh[nf][sel], bh[nf][sel + 2]);
                    mma16816(acc[mi][ni], ah[mi], bl[nf][sel], bl[nf][sel + 2]);
                    mma16816(acc[mi][ni], al[mi], bh[nf][sel], bh[nf][sel + 2]);
                }
        }
    }

    // epilogue: C frag -> fp32 stores (row m = l/4 (+8), col n = (l%4)*2)
    #pragma unroll
    for (int mi = 0; mi < 4; mi++) {
        int mrow0 = m0 + wm + mi * 16 + (lane >> 2);
        #pragma unroll
        for (int half = 0; half < 2; half++) {
            int m = mrow0 + half * 8;
            if (m < NN) {
                float* op = O + (size_t)m * DOUT + col0 + wn + (lane & 3) * 2;
                #pragma unroll
                for (int ni = 0; ni < 4; ni++) {
                    float2 v = make_float2(acc[mi][ni][half * 2], acc[mi][ni][half * 2 + 1]);
                    *(float2*)(op + ni * 8) = v;
                }
            }
        }
    }
}

// ---------------- fused attention softmax + aggregation ----------------
__global__ __launch_bounds__(256) void k_aggregate(
    const float* __restrict__ att,
    const float* __restrict__ bias,
    float* __restrict__ out)
{
    const int gw = (blockIdx.x * blockDim.x + threadIdx.x) >> 5;
    const int lane = threadIdx.x & 31;
    if (gw >= NN) return;

    const int base = lane * 8;
    float4 xr0 = *(const float4*)(g_xr + (size_t)gw * DOUT + base);
    float4 xr1 = *(const float4*)(g_xr + (size_t)gw * DOUT + base + 4);
    float4 at0 = *(const float4*)(att + base);
    float4 at1 = *(const float4*)(att + base + 4);

    float a0 = 0.f, a1 = 0.f, a2 = 0.f, a3 = 0.f;
    float a4 = 0.f, a5 = 0.f, a6 = 0.f, a7 = 0.f;
    float denom = 0.f;

    const int s = g_starts[gw];
    const int cnt = g_counts[gw];

    for (int b = 0; b < cnt; b += 32) {
        int m = cnt - b; if (m > 32) m = 32;
        int sidx = 0;
        if (b + lane < cnt) sidx = g_src_sorted[s + b + lane];

        int src0 = __shfl_sync(0xffffffffu, sidx, 0);
        const float4* xp = (const float4*)(g_xl + (size_t)src0 * DOUT + base);
        float4 v0 = __ldg(xp);
        float4 v1 = __ldg(xp + 1);

        for (int j = 0; j < m; j++) {
            float4 c0 = v0, c1 = v1;
            if (j + 1 < m) {
                int srcn = __shfl_sync(0xffffffffu, sidx, j + 1);
                const float4* xn = (const float4*)(g_xl + (size_t)srcn * DOUT + base);
                v0 = __ldg(xn);
                v1 = __ldg(xn + 1);
            }

            float e = 0.f, z, l;
            z = c0.x + xr0.x; l = fmaxf(z, NEG * z); e = fmaf(l, at0.x, e);
            z = c0.y + xr0.y; l = fmaxf(z, NEG * z); e = fmaf(l, at0.y, e);
            z = c0.z + xr0.z; l = fmaxf(z, NEG * z); e = fmaf(l, at0.z, e);
            z = c0.w + xr0.w; l = fmaxf(z, NEG * z); e = fmaf(l, at0.w, e);
            z = c1.x + xr1.x; l = fmaxf(z, NEG * z); e = fmaf(l, at1.x, e);
            z = c1.y + xr1.y; l = fmaxf(z, NEG * z); e = fmaf(l, at1.y, e);
            z = c1.z + xr1.z; l = fmaxf(z, NEG * z); e = fmaf(l, at1.z, e);
            z = c1.w + xr1.w; l = fmaxf(z, NEG * z); e = fmaf(l, at1.w, e);

            e += __shfl_xor_sync(0xffffffffu, e, 16);
            e += __shfl_xor_sync(0xffffffffu, e, 8);
            e += __shfl_xor_sync(0xffffffffu, e, 4);
            e += __shfl_xor_sync(0xffffffffu, e, 2);
            e += __shfl_xor_sync(0xffffffffu, e, 1);

            float p = __expf(e);
            denom += p;
            a0 = fmaf(p, c0.x, a0); a1 = fmaf(p, c0.y, a1);
            a2 = fmaf(p, c0.z, a2); a3 = fmaf(p, c0.w, a3);
            a4 = fmaf(p, c1.x, a4); a5 = fmaf(p, c1.y, a5);
            a6 = fmaf(p, c1.z, a6); a7 = fmaf(p, c1.w, a7);
        }
    }

    float r = 1.0f / denom;
    float4 b0 = *(const float4*)(bias + base);
    float4 b1 = *(const float4*)(bias + base + 4);
    float4 o0, o1;
    o0.x = fmaf(a0, r, b0.x); o0.y = fmaf(a1, r, b0.y);
    o0.z = fmaf(a2, r, b0.z); o0.w = fmaf(a3, r, b0.w);
    o1.x = fmaf(a4, r, b1.x); o1.y = fmaf(a5, r, b1.y);
    o1.z = fmaf(a6, r, b1.z); o1.w = fmaf(a7, r, b1.w);
    float* op = out + (size_t)gw * DOUT + base;
    *(float4*)(op)     = o0;
    *(float4*)(op + 4) = o1;
}

// ---------------- launch ----------------
extern "C" void kernel_launch(void* const* d_in, const int* in_sizes, int n_in,
                              void* d_out, int out_size) {
    const float* x    = (const float*)d_in[0];
    const void*  ei   = d_in[1];
    const float* Wl   = (const float*)d_in[2];
    const float* Wr   = (const float*)d_in[3];
    const float* att  = (const float*)d_in[4];
    const float* bias = (const float*)d_in[5];
    float*       out  = (float*)d_out;

    cudaFuncSetAttribute(k_mma, cudaFuncAttributeMaxDynamicSharedMemorySize, SMEM_TOT);

    // 1-5: conversions + CSR front half (k_mma is launch #6 -> profiled by -s 5 -c 1)
    {
        size_t tot = (size_t)NN * (KP / 4);
        k_convA<<<(unsigned)((tot + 255) / 256), 256>>>(x);
    }
    k_convB<<<(512 * KP + 255) / 256, 256>>>(Wl, Wr);
    k_detect<<<1, 32>>>((const int*)ei);
    k_zero_counts<<<(NN + 255) / 256, 256>>>();
    k_hist<<<(TOT + 255) / 256, 256>>>(ei);

    // 6: split-bf16 HMMA GEMM (xl / xr); column-variant fast grid dim for L2 A-reuse
    k_mma<<<dim3(4, NNP / 128), 256, SMEM_TOT>>>();

    // CSR back half
    k_scan1<<<NBS, 512>>>();
    k_scan2<<<1, 32>>>();
    k_scan3<<<(NN + 255) / 256, 256>>>();
    k_scatter<<<(TOT + 255) / 256, 256>>>(ei);

    // fused softmax + aggregation
    k_aggregate<<<(NN * 32) / 256, 256>>>(att, bias, out);
}